// round 13
// baseline (speedup 1.0000x reference)
#include <cuda_runtime.h>
#include <mma.h>
#include <cstdint>
#include <math.h>

using namespace nvcuda;

// Problem constants
#define BATCH 2
#define SEQ   2048
#define SIZE  1024
#define HEADS 16
#define HDIM  64
#define M_TOK (BATCH * SEQ)
#define BH    (BATCH * HEADS)
#define NQT   (SEQ / 128)     // 16 q-tiles

// -------- scratch (device globals; no allocations allowed) --------
__device__ float g_q[(size_t)BH * SEQ * HDIM];        // [bh, s, d] (tf32-rounded)
__device__ float g_k[(size_t)BH * SEQ * HDIM];
__device__ float g_v[(size_t)BH * SEQ * HDIM];
__device__ float g_oh[(size_t)BH * SEQ * HDIM];       // (tf32-rounded)
__device__ float g_psum[(size_t)BH * SEQ * NQT];
__device__ float g_attn_scratch[(size_t)BH * SEQ * SEQ];
__device__ float g_out_scratch[(size_t)M_TOK * SIZE];
// tf32-rounded copies of harness inputs
__device__ float g_cq[(size_t)M_TOK * SIZE];
__device__ float g_ck[(size_t)M_TOK * SIZE];
__device__ float g_cv[(size_t)M_TOK * SIZE];
__device__ float g_cwq[(size_t)SIZE * SIZE];
__device__ float g_cwk[(size_t)SIZE * SIZE];
__device__ float g_cwv[(size_t)SIZE * SIZE];
__device__ float g_cwo[(size_t)SIZE * SIZE];

__device__ __forceinline__ float f2tf32f(float x) {
    uint32_t r;
    asm("cvt.rna.tf32.f32 %0, %1;" : "=r"(r) : "f"(x));
    return __uint_as_float(r);
}
__device__ __forceinline__ uint32_t smem_u32(const void* p) {
    uint32_t a;
    asm("{ .reg .u64 t; cvta.to.shared.u64 t, %1; cvt.u32.u64 %0, t; }" : "=r"(a) : "l"(p));
    return a;
}
__device__ __forceinline__ void cpa16(float* smem_dst, const float* gsrc) {
    uint32_t d = smem_u32(smem_dst);
    asm volatile("cp.async.cg.shared.global [%0], [%1], 16;" :: "r"(d), "l"(gsrc));
}
__device__ __forceinline__ void cpa_commit() {
    asm volatile("cp.async.commit_group;");
}
template<int N>
__device__ __forceinline__ void cpa_wait() {
    asm volatile("cp.async.wait_group %0;" :: "n"(N));
}

typedef wmma::fragment<wmma::matrix_a, 16, 16, 8, wmma::precision::tf32, wmma::row_major> FragA;
typedef wmma::fragment<wmma::matrix_b, 16, 16, 8, wmma::precision::tf32, wmma::col_major> FragBc;
typedef wmma::fragment<wmma::matrix_b, 16, 16, 8, wmma::precision::tf32, wmma::row_major> FragBr;
typedef wmma::fragment<wmma::accumulator, 16, 16, 8, float> FragC;

#define LDA 36   // smem leading dim for 32-wide K tiles (pad 4)
#define LDQ 68   // smem leading dim for 64-wide tiles (pad 4)
#define LDV 68

// dynamic smem sizes (bytes)
#define SMEM_GEMM   ((2*128*LDA*2 + 4*272) * 4)              // 78080
#define SMEM_SCORES ((2*128*LDQ + 8*272 + 128*4) * 4)        // 80384
#define SMEM_ATTNV  ((3*128*LDA + 3*32*LDV + 8*272) * 4)     // 90112

// ==================================================================
// cvt7: round 7 arrays to tf32-in-fp32 (z selects array).
// ==================================================================
__global__ void __launch_bounds__(256) cvt7_tf32(
    const float* __restrict__ s0, const float* __restrict__ s1, const float* __restrict__ s2,
    const float* __restrict__ s3, const float* __restrict__ s4, const float* __restrict__ s5,
    const float* __restrict__ s6,
    float* __restrict__ d0, float* __restrict__ d1, float* __restrict__ d2,
    float* __restrict__ d3, float* __restrict__ d4, float* __restrict__ d5,
    float* __restrict__ d6) {
    const int z = blockIdx.z;
    const float* src; float* dst; int n4;
    switch (z) {
        case 0: src = s0; dst = d0; n4 = M_TOK * SIZE / 4; break;
        case 1: src = s1; dst = d1; n4 = M_TOK * SIZE / 4; break;
        case 2: src = s2; dst = d2; n4 = M_TOK * SIZE / 4; break;
        case 3: src = s3; dst = d3; n4 = SIZE * SIZE / 4; break;
        case 4: src = s4; dst = d4; n4 = SIZE * SIZE / 4; break;
        case 5: src = s5; dst = d5; n4 = SIZE * SIZE / 4; break;
        default: src = s6; dst = d6; n4 = SIZE * SIZE / 4; break;
    }
    int stride = gridDim.x * 256;
    for (int i = blockIdx.x * 256 + threadIdx.x; i < n4; i += stride) {
        float4 t = reinterpret_cast<const float4*>(src)[i];
        reinterpret_cast<float4*>(dst)[i] =
            make_float4(f2tf32f(t.x), f2tf32f(t.y), f2tf32f(t.z), f2tf32f(t.w));
    }
}

// ==================================================================
// 4-warp GEMM core (cp.async double-buffered): CTA 128x128, warp 64x64.
// ==================================================================
template<int IN_MODE, int OUT_MODE>
__device__ __forceinline__ void gemm_core(const float* __restrict__ X,
                                          const float* __restrict__ W,
                                          const float* __restrict__ bias,
                                          float* __restrict__ Y,
                                          int bm, int bn, float* smem) {
    float* As = smem;
    float* Bs = As + 2 * 128 * LDA;
    float* stage = Bs + 2 * 128 * LDA;

    const int tid = threadIdx.x, wid = tid >> 5, lane = tid & 31;
    const int wm0 = (wid & 1) * 64, wn0 = (wid >> 1) * 64;

    FragC acc[4][4];
    #pragma unroll
    for (int mt = 0; mt < 4; mt++)
        #pragma unroll
        for (int nt = 0; nt < 4; nt++) wmma::fill_fragment(acc[mt][nt], 0.0f);

    auto xsrc = [&](int kc, int i, int j) -> const float* {
        if (IN_MODE == 0) {
            return X + (size_t)(bm * 128 + i) * 1024 + kc + j;
        } else {
            int gm = bm * 128 + i;
            int b = gm >> 11, s = gm & 2047;
            int h = kc >> 6, d0 = (kc & 63) + j;
            return X + ((((size_t)b * HEADS + h) * SEQ + s) << 6) + d0;
        }
    };

    auto issue_chunk = [&](int kc, float* Ad, float* Bd) {
        #pragma unroll
        for (int l = 0; l < 8; l++) {
            int v = tid + l * 128;
            int i = v >> 3, j = (v & 7) * 4;
            cpa16(&Ad[i * LDA + j], xsrc(kc, i, j));
            cpa16(&Bd[i * LDA + j], W + (size_t)(bn * 128 + i) * 1024 + kc + j);
        }
        cpa_commit();
    };

    issue_chunk(0, As, Bs);

    for (int c = 0; c < 32; c++) {
        const int buf = c & 1;
        const bool nxt = (c + 1 < 32);
        if (nxt) {
            issue_chunk((c + 1) * 32, As + (buf ^ 1) * 128 * LDA,
                        Bs + (buf ^ 1) * 128 * LDA);
            cpa_wait<1>();
        } else {
            cpa_wait<0>();
        }
        __syncthreads();

        const float* Ab = As + buf * 128 * LDA;
        const float* Bb = Bs + buf * 128 * LDA;
        #pragma unroll
        for (int ks = 0; ks < 32; ks += 8) {
            FragA af[4];
            FragBc bf[4];
            #pragma unroll
            for (int mt = 0; mt < 4; mt++)
                wmma::load_matrix_sync(af[mt], &Ab[(wm0 + mt * 16) * LDA + ks], LDA);
            #pragma unroll
            for (int nt = 0; nt < 4; nt++)
                wmma::load_matrix_sync(bf[nt], &Bb[(wn0 + nt * 16) * LDA + ks], LDA);
            #pragma unroll
            for (int mt = 0; mt < 4; mt++)
                #pragma unroll
                for (int nt = 0; nt < 4; nt++)
                    wmma::mma_sync(acc[mt][nt], af[mt], bf[nt], acc[mt][nt]);
        }
        __syncthreads();
    }

    float* st = stage + wid * 272;
    #pragma unroll
    for (int mt = 0; mt < 4; mt++) {
        #pragma unroll
        for (int nt = 0; nt < 4; nt++) {
            wmma::store_matrix_sync(st, acc[mt][nt], 16, wmma::mem_row_major);
            __syncwarp();
            int r = lane >> 1, c8 = (lane & 1) * 8;
            int gm = bm * 128 + wm0 + mt * 16 + r;
            int gn_t = bn * 128 + wn0 + nt * 16;
            float out[8];
            #pragma unroll
            for (int jj = 0; jj < 8; jj++) {
                float vv = st[r * 16 + c8 + jj] + bias[gn_t + c8 + jj];
                out[jj] = (OUT_MODE == 1) ? f2tf32f(vv) : vv;
            }
            float* dst;
            if (OUT_MODE == 0) {
                dst = Y + (size_t)gm * SIZE + gn_t + c8;
            } else {
                int b = gm >> 11, s = gm & 2047;
                int h = gn_t >> 6, d0 = (gn_t & 63) + c8;
                dst = Y + ((((size_t)b * HEADS + h) * SEQ + s) << 6) + d0;
            }
            *reinterpret_cast<float4*>(dst)     = make_float4(out[0], out[1], out[2], out[3]);
            *reinterpret_cast<float4*>(dst + 4) = make_float4(out[4], out[5], out[6], out[7]);
            __syncwarp();
        }
    }
}

__global__ void __launch_bounds__(128, 2) proj3_wmma(
    const float* __restrict__ X0, const float* __restrict__ X1, const float* __restrict__ X2,
    const float* __restrict__ W0, const float* __restrict__ W1, const float* __restrict__ W2,
    const float* __restrict__ b0, const float* __restrict__ b1, const float* __restrict__ b2,
    float* __restrict__ Y0, float* __restrict__ Y1, float* __restrict__ Y2) {
    extern __shared__ __align__(16) float smem[];
    const int z = blockIdx.z;
    const float* X = (z == 0) ? X0 : (z == 1) ? X1 : X2;
    const float* W = (z == 0) ? W0 : (z == 1) ? W1 : W2;
    const float* bias = (z == 0) ? b0 : (z == 1) ? b1 : b2;
    float* Y = (z == 0) ? Y0 : (z == 1) ? Y1 : Y2;
    gemm_core<0, 1>(X, W, bias, Y, blockIdx.y, blockIdx.x, smem);
}

__global__ void __launch_bounds__(128, 2) outproj_wmma(const float* __restrict__ Xh,
                                                       const float* __restrict__ W,
                                                       const float* __restrict__ bias,
                                                       float* __restrict__ Y) {
    extern __shared__ __align__(16) float smem[];
    gemm_core<1, 0>(Xh, W, bias, Y, blockIdx.y, blockIdx.x, smem);
}

// ==================================================================
// rowsum_pass: lower-tri tiles only. MMA S, exp, row partial sums ->
// g_psum. NO attn writes.
// ==================================================================
__global__ void __launch_bounds__(256, 2) rowsum_pass(const float* __restrict__ Q,
                                                      const float* __restrict__ Kh,
                                                      float* __restrict__ psum) {
    const int bn = blockIdx.x, bm = blockIdx.y, bh = blockIdx.z;
    if (bn > bm) return;
    const int tid = threadIdx.x;

    extern __shared__ __align__(16) float smem[];
    float* Qs = smem;                      // 128*LDQ
    float* Ks = Qs + 128 * LDQ;            // 128*LDQ
    float* stage = Ks + 128 * LDQ;         // 8*272
    float* psums_sm = stage + 8 * 272;     // 128*4

    const int wid = tid >> 5, lane = tid & 31;
    const int wm0 = (wid & 1) * 64, wng = wid >> 1;
    const int wn0 = wng * 32;
    const float* q = Q + (size_t)bh * SEQ * HDIM;
    const float* k = Kh + (size_t)bh * SEQ * HDIM;
    const bool diag = (bm == bn);

    #pragma unroll
    for (int l = 0; l < 8; l++) {
        int f4 = tid + l * 256;
        int i = f4 >> 4, j = (f4 & 15) * 4;
        cpa16(&Qs[i * LDQ + j], q + (size_t)(bm * 128 + i) * HDIM + j);
        cpa16(&Ks[i * LDQ + j], k + (size_t)(bn * 128 + i) * HDIM + j);
    }
    cpa_commit();
    cpa_wait<0>();
    __syncthreads();

    FragC acc[4][2];
    #pragma unroll
    for (int mt = 0; mt < 4; mt++)
        #pragma unroll
        for (int nt = 0; nt < 2; nt++) wmma::fill_fragment(acc[mt][nt], 0.0f);

    #pragma unroll
    for (int ks = 0; ks < 64; ks += 8) {
        FragA af[4];
        FragBc bf[2];
        #pragma unroll
        for (int mt = 0; mt < 4; mt++)
            wmma::load_matrix_sync(af[mt], &Qs[(wm0 + mt * 16) * LDQ + ks], LDQ);
        #pragma unroll
        for (int nt = 0; nt < 2; nt++)
            wmma::load_matrix_sync(bf[nt], &Ks[(wn0 + nt * 16) * LDQ + ks], LDQ);
        #pragma unroll
        for (int mt = 0; mt < 4; mt++)
            #pragma unroll
            for (int nt = 0; nt < 2; nt++)
                wmma::mma_sync(acc[mt][nt], af[mt], bf[nt], acc[mt][nt]);
    }

    float* st = stage + wid * 272;
    #pragma unroll
    for (int mt = 0; mt < 4; mt++) {
        float rowsum = 0.f;
        #pragma unroll
        for (int nt = 0; nt < 2; nt++) {
            wmma::store_matrix_sync(st, acc[mt][nt], 16, wmma::mem_row_major);
            __syncwarp();
            int r = lane >> 1, c8 = (lane & 1) * 8;
            int gq = bm * 128 + wm0 + mt * 16 + r;
            int gk0 = bn * 128 + wn0 + nt * 16 + c8;
            #pragma unroll
            for (int jj = 0; jj < 8; jj++) {
                float s = st[r * 16 + c8 + jj] * 0.125f;
                float v = __expf(s);
                if (diag && (gk0 + jj > gq)) v = 0.f;
                rowsum += v;
            }
            __syncwarp();
        }
        rowsum += __shfl_xor_sync(~0u, rowsum, 1);
        if ((lane & 1) == 0)
            psums_sm[(wm0 + mt * 16 + (lane >> 1)) * 4 + wng] = rowsum;
    }
    __syncthreads();
    if (tid < 128) {
        float s = psums_sm[tid * 4 + 0] + psums_sm[tid * 4 + 1]
                + psums_sm[tid * 4 + 2] + psums_sm[tid * 4 + 3];
        psum[((size_t)(bh * NQT + bm) * 128 + tid) * NQT + bn] = s;
    }
}

// ==================================================================
// scores_p: write FINAL P = exp(S/8) * il directly (il from psum).
// Upper-tri CTAs zero-fill.
// ==================================================================
__global__ void __launch_bounds__(256, 2) scores_p(const float* __restrict__ Q,
                                                   const float* __restrict__ Kh,
                                                   const float* __restrict__ psum,
                                                   float* __restrict__ attn) {
    const int bn = blockIdx.x, bm = blockIdx.y, bh = blockIdx.z;
    const int tid = threadIdx.x;

    if (bn > bm) {
        const float4 z4 = {0.f, 0.f, 0.f, 0.f};
        float* base = attn + ((size_t)bh * SEQ + bm * 128) * SEQ + bn * 128;
        #pragma unroll
        for (int l = 0; l < 16; l++) {
            int idx = tid + l * 256;
            int i = idx >> 5, j4 = idx & 31;
            *reinterpret_cast<float4*>(base + (size_t)i * SEQ + j4 * 4) = z4;
        }
        return;
    }

    extern __shared__ __align__(16) float smem[];
    float* Qs = smem;                      // 128*LDQ
    float* Ks = Qs + 128 * LDQ;            // 128*LDQ
    float* stage = Ks + 128 * LDQ;         // 8*272
    float* ilrow = stage + 8 * 272;        // 128

    const int wid = tid >> 5, lane = tid & 31;
    const int wm0 = (wid & 1) * 64, wn0 = (wid >> 1) * 32;
    const float* q = Q + (size_t)bh * SEQ * HDIM;
    const float* k = Kh + (size_t)bh * SEQ * HDIM;
    const bool diag = (bm == bn);

    #pragma unroll
    for (int l = 0; l < 8; l++) {
        int f4 = tid + l * 256;
        int i = f4 >> 4, j = (f4 & 15) * 4;
        cpa16(&Qs[i * LDQ + j], q + (size_t)(bm * 128 + i) * HDIM + j);
        cpa16(&Ks[i * LDQ + j], k + (size_t)(bn * 128 + i) * HDIM + j);
    }
    cpa_commit();

    if (tid < 128) {
        const float* ps = psum + ((size_t)(bh * NQT + bm) * 128 + tid) * NQT;
        float s = 0.f;
        for (int t = 0; t <= bm; t++) s += ps[t];
        ilrow[tid] = 1.0f / s;
    }

    cpa_wait<0>();
    __syncthreads();

    FragC acc[4][2];
    #pragma unroll
    for (int mt = 0; mt < 4; mt++)
        #pragma unroll
        for (int nt = 0; nt < 2; nt++) wmma::fill_fragment(acc[mt][nt], 0.0f);

    #pragma unroll
    for (int ks = 0; ks < 64; ks += 8) {
        FragA af[4];
        FragBc bf[2];
        #pragma unroll
        for (int mt = 0; mt < 4; mt++)
            wmma::load_matrix_sync(af[mt], &Qs[(wm0 + mt * 16) * LDQ + ks], LDQ);
        #pragma unroll
        for (int nt = 0; nt < 2; nt++)
            wmma::load_matrix_sync(bf[nt], &Ks[(wn0 + nt * 16) * LDQ + ks], LDQ);
        #pragma unroll
        for (int mt = 0; mt < 4; mt++)
            #pragma unroll
            for (int nt = 0; nt < 2; nt++)
                wmma::mma_sync(acc[mt][nt], af[mt], bf[nt], acc[mt][nt]);
    }

    float* st = stage + wid * 272;
    #pragma unroll
    for (int mt = 0; mt < 4; mt++) {
        #pragma unroll
        for (int nt = 0; nt < 2; nt++) {
            wmma::store_matrix_sync(st, acc[mt][nt], 16, wmma::mem_row_major);
            __syncwarp();
            int r = lane >> 1, c8 = (lane & 1) * 8;
            int rloc = wm0 + mt * 16 + r;
            int gq = bm * 128 + rloc;
            int gk0 = bn * 128 + wn0 + nt * 16 + c8;
            float il = ilrow[rloc];
            float e[8];
            #pragma unroll
            for (int jj = 0; jj < 8; jj++) {
                float s = st[r * 16 + c8 + jj] * 0.125f;
                float v = __expf(s) * il;
                if (diag && (gk0 + jj > gq)) v = 0.f;
                e[jj] = v;
            }
            float* dst = attn + ((size_t)bh * SEQ + gq) * SEQ + gk0;
            *reinterpret_cast<float4*>(dst)     = make_float4(e[0], e[1], e[2], e[3]);
            *reinterpret_cast<float4*>(dst + 4) = make_float4(e[4], e[5], e[6], e[7]);
            __syncwarp();
        }
    }
}

// ==================================================================
// attnv_p: read-only on attn (P final). cp.async 3-stage pipeline.
// O = P @ V, stored tf32-rounded to Oh. One syncthreads per chunk.
// ==================================================================
__global__ void __launch_bounds__(256, 2) attnv_p(const float* __restrict__ attn,
                                                  const float* __restrict__ V,
                                                  float* __restrict__ Oh) {
    const int qt = (NQT - 1) - blockIdx.x;   // big tiles first
    const int bh = blockIdx.y;
    extern __shared__ __align__(16) float smem[];
    float* As = smem;                        // 3 * 128*LDA
    float* Vs = As + 3 * 128 * LDA;          // 3 * 32*LDV
    float* stage = Vs + 3 * 32 * LDV;        // 8*272

    const int tid = threadIdx.x, wid = tid >> 5, lane = tid & 31;
    const int wm0 = (wid & 3) * 32, wn0 = (wid >> 2) * 32;
    const float* a = attn + ((size_t)bh * SEQ + qt * 128) * SEQ;
    const float* v = V + (size_t)bh * SEQ * HDIM;

    FragC acc[2][2];
    #pragma unroll
    for (int mt = 0; mt < 2; mt++)
        #pragma unroll
        for (int nt = 0; nt < 2; nt++) wmma::fill_fragment(acc[mt][nt], 0.0f);

    const int NCH = (qt + 1) * 4;            // 32-col chunks (>= 4)

    auto issue = [&](int c) {
        const int kc = c * 32;
        float* Ad = As + (c % 3) * 128 * LDA;
        float* Vd = Vs + (c % 3) * 32 * LDV;
        #pragma unroll
        for (int l = 0; l < 4; l++) {
            int vv = tid + l * 256;
            int i = vv >> 3, j = (vv & 7) * 4;
            cpa16(&Ad[i * LDA + j], a + (size_t)i * SEQ + kc + j);
        }
        #pragma unroll
        for (int l = 0; l < 2; l++) {
            int vv = tid + l * 256;
            int i = vv >> 4, j = (vv & 15) * 4;
            cpa16(&Vd[i * LDV + j], v + (size_t)(kc + i) * HDIM + j);
        }
        cpa_commit();
    };

    issue(0);
    issue(1);

    for (int c = 0; c < NCH; c++) {
        cpa_wait<1>();          // stage c complete
        __syncthreads();        // all warps see stage c; prior MMA readers done
        if (c + 2 < NCH) issue(c + 2);   // buf (c+2)%3 freed by iter c-1

        const float* Ab = As + (c % 3) * 128 * LDA;
        const float* Vb = Vs + (c % 3) * 32 * LDV;
        #pragma unroll
        for (int ks = 0; ks < 32; ks += 8) {
            FragA af[2];
            FragBr bf[2];
            #pragma unroll
            for (int mt = 0; mt < 2; mt++)
                wmma::load_matrix_sync(af[mt], &Ab[(wm0 + mt * 16) * LDA + ks], LDA);
            #pragma unroll
            for (int nt = 0; nt < 2; nt++)
                wmma::load_matrix_sync(bf[nt], &Vb[ks * LDV + wn0 + nt * 16], LDV);
            #pragma unroll
            for (int mt = 0; mt < 2; mt++)
                #pragma unroll
                for (int nt = 0; nt < 2; nt++)
                    wmma::mma_sync(acc[mt][nt], af[mt], bf[nt], acc[mt][nt]);
        }
    }
    __syncthreads();

    float* st = stage + wid * 272;
    #pragma unroll
    for (int mt = 0; mt < 2; mt++) {
        #pragma unroll
        for (int nt = 0; nt < 2; nt++) {
            wmma::store_matrix_sync(st, acc[mt][nt], 16, wmma::mem_row_major);
            __syncwarp();
            int r = lane >> 1, c8 = (lane & 1) * 8;
            int gq = qt * 128 + wm0 + mt * 16 + r;
            int d0 = wn0 + nt * 16 + c8;
            float out[8];
            #pragma unroll
            for (int jj = 0; jj < 8; jj++)
                out[jj] = f2tf32f(st[r * 16 + c8 + jj]);   // pre-rounded for outproj
            float* dst = Oh + (((size_t)bh * SEQ + gq) << 6) + d0;
            *reinterpret_cast<float4*>(dst)     = make_float4(out[0], out[1], out[2], out[3]);
            *reinterpret_cast<float4*>(dst + 4) = make_float4(out[4], out[5], out[6], out[7]);
            __syncwarp();
        }
    }
}

// ==================================================================
// host launcher
// ==================================================================
extern "C" void kernel_launch(void* const* d_in, const int* in_sizes, int n_in,
                              void* d_out, int out_size) {
    const float* key   = (const float*)d_in[0];
    const float* value = (const float*)d_in[1];
    const float* query = (const float*)d_in[2];
    const float* Wk = (const float*)d_in[4];
    const float* bk = (const float*)d_in[5];
    const float* Wv = (const float*)d_in[6];
    const float* bv = (const float*)d_in[7];
    const float* Wq = (const float*)d_in[8];
    const float* bq = (const float*)d_in[9];
    const float* Wo = (const float*)d_in[10];
    const float* bo = (const float*)d_in[11];

    float *qh, *kh, *vh, *oh, *psum, *attn_scr, *out_scr;
    float *cq, *ck, *cv, *cwq, *cwk, *cwv, *cwo;
    cudaGetSymbolAddress((void**)&qh, g_q);
    cudaGetSymbolAddress((void**)&kh, g_k);
    cudaGetSymbolAddress((void**)&vh, g_v);
    cudaGetSymbolAddress((void**)&oh, g_oh);
    cudaGetSymbolAddress((void**)&psum, g_psum);
    cudaGetSymbolAddress((void**)&attn_scr, g_attn_scratch);
    cudaGetSymbolAddress((void**)&out_scr, g_out_scratch);
    cudaGetSymbolAddress((void**)&cq, g_cq);
    cudaGetSymbolAddress((void**)&ck, g_ck);
    cudaGetSymbolAddress((void**)&cv, g_cv);
    cudaGetSymbolAddress((void**)&cwq, g_cwq);
    cudaGetSymbolAddress((void**)&cwk, g_cwk);
    cudaGetSymbolAddress((void**)&cwv, g_cwv);
    cudaGetSymbolAddress((void**)&cwo, g_cwo);

    const long long OUT_ELE  = (long long)M_TOK * SIZE;
    const long long ATTN_ELE = (long long)BH * SEQ * SEQ;

    float* dout = (float*)d_out;
    float* outp;
    float* attnp;
    if ((long long)out_size >= OUT_ELE + ATTN_ELE) {
        outp = dout; attnp = dout + OUT_ELE;
    } else if ((long long)out_size == ATTN_ELE) {
        attnp = dout; outp = out_scr;
    } else {
        outp = dout; attnp = attn_scr;
    }

    cudaFuncSetAttribute(proj3_wmma,   cudaFuncAttributeMaxDynamicSharedMemorySize, SMEM_GEMM);
    cudaFuncSetAttribute(outproj_wmma, cudaFuncAttributeMaxDynamicSharedMemorySize, SMEM_GEMM);
    cudaFuncSetAttribute(rowsum_pass,  cudaFuncAttributeMaxDynamicSharedMemorySize, SMEM_SCORES);
    cudaFuncSetAttribute(scores_p,     cudaFuncAttributeMaxDynamicSharedMemorySize, SMEM_SCORES);
    cudaFuncSetAttribute(attnv_p,      cudaFuncAttributeMaxDynamicSharedMemorySize, SMEM_ATTNV);

    dim3 thrG(128);
    dim3 thr(256);

    // 0) round inputs + weights to tf32 once
    dim3 gCvt(512, 1, 7);
    cvt7_tf32<<<gCvt, thr>>>(query, key, value, Wq, Wk, Wv, Wo,
                             cq, ck, cv, cwq, cwk, cwv, cwo);

    // 1) projections
    dim3 gProj3(SIZE / 128, M_TOK / 128, 3);        // (8, 32, 3)
    proj3_wmma<<<gProj3, thrG, SMEM_GEMM>>>(cq, ck, cv,
                                            cwq, cwk, cwv,
                                            bq, bk, bv,
                                            qh, kh, vh);

    // 2a) row sums (no attn writes)
    dim3 gScores(NQT, NQT, BH);                     // (16, 16, 32)
    rowsum_pass<<<gScores, thr, SMEM_SCORES>>>(qh, kh, psum);

    // 2b) final P written once
    scores_p<<<gScores, thr, SMEM_SCORES>>>(qh, kh, psum, attnp);

    // 3) O = P @ V (read-only on attn)
    dim3 gAV(NQT, BH);                              // (16, 32)
    attnv_p<<<gAV, thr, SMEM_ATTNV>>>(attnp, vh, oh);

    // 4) output projection
    dim3 gOut(SIZE / 128, M_TOK / 128);             // (8, 32)
    outproj_wmma<<<gOut, thrG, SMEM_GEMM>>>(oh, cwo, bo, outp);
}

// round 14
// speedup vs baseline: 1.1766x; 1.1766x over previous
#include <cuda_runtime.h>
#include <mma.h>
#include <cstdint>
#include <math.h>

using namespace nvcuda;

// Problem constants
#define BATCH 2
#define SEQ   2048
#define SIZE  1024
#define HEADS 16
#define HDIM  64
#define M_TOK (BATCH * SEQ)
#define BH    (BATCH * HEADS)
#define NQT   (SEQ / 128)     // 16 q-tiles

// -------- scratch (device globals; no allocations allowed) --------
__device__ float g_q[(size_t)BH * SEQ * HDIM];        // [bh, s, d] (tf32-rounded)
__device__ float g_k[(size_t)BH * SEQ * HDIM];
__device__ float g_v[(size_t)BH * SEQ * HDIM];
__device__ float g_oh[(size_t)BH * SEQ * HDIM];       // (tf32-rounded)
__device__ float g_psum[(size_t)BH * SEQ * NQT];
__device__ float g_attn_scratch[(size_t)BH * SEQ * SEQ];
__device__ float g_out_scratch[(size_t)M_TOK * SIZE];
// tf32-rounded copies of harness inputs
__device__ float g_cq[(size_t)M_TOK * SIZE];
__device__ float g_ck[(size_t)M_TOK * SIZE];
__device__ float g_cv[(size_t)M_TOK * SIZE];
__device__ float g_cwq[(size_t)SIZE * SIZE];
__device__ float g_cwk[(size_t)SIZE * SIZE];
__device__ float g_cwv[(size_t)SIZE * SIZE];
__device__ float g_cwo[(size_t)SIZE * SIZE];

__device__ __forceinline__ float f2tf32f(float x) {
    uint32_t r;
    asm("cvt.rna.tf32.f32 %0, %1;" : "=r"(r) : "f"(x));
    return __uint_as_float(r);
}
__device__ __forceinline__ uint32_t smem_u32(const void* p) {
    uint32_t a;
    asm("{ .reg .u64 t; cvta.to.shared.u64 t, %1; cvt.u32.u64 %0, t; }" : "=r"(a) : "l"(p));
    return a;
}
__device__ __forceinline__ void cpa16(float* smem_dst, const float* gsrc) {
    uint32_t d = smem_u32(smem_dst);
    asm volatile("cp.async.cg.shared.global [%0], [%1], 16;" :: "r"(d), "l"(gsrc));
}
__device__ __forceinline__ void cpa_commit() {
    asm volatile("cp.async.commit_group;");
}
template<int N>
__device__ __forceinline__ void cpa_wait() {
    asm volatile("cp.async.wait_group %0;" :: "n"(N));
}

typedef wmma::fragment<wmma::matrix_a, 16, 16, 8, wmma::precision::tf32, wmma::row_major> FragA;
typedef wmma::fragment<wmma::matrix_b, 16, 16, 8, wmma::precision::tf32, wmma::col_major> FragBc;
typedef wmma::fragment<wmma::matrix_b, 16, 16, 8, wmma::precision::tf32, wmma::row_major> FragBr;
typedef wmma::fragment<wmma::accumulator, 16, 16, 8, float> FragC;

#define LDA 36   // smem leading dim for 32-wide K tiles (pad 4)
#define LDQ 68   // smem leading dim for 64-wide tiles (pad 4)
#define LDV 68

// dynamic smem sizes (bytes)
#define SMEM_GEMM   ((2*128*LDA*2 + 4*272) * 4)                   // 78080
#define SMEM_SCORES ((2*128*LDQ + 8*272 + 128*4) * 4)             // 80384
#define SMEM_AV2    ((2*128*LDA + 2*32*LDV + 4*272 + 128) * 4)    // 59136

// ==================================================================
// cvt7: round 7 arrays to tf32-in-fp32 (z selects array).
// ==================================================================
__global__ void __launch_bounds__(256) cvt7_tf32(
    const float* __restrict__ s0, const float* __restrict__ s1, const float* __restrict__ s2,
    const float* __restrict__ s3, const float* __restrict__ s4, const float* __restrict__ s5,
    const float* __restrict__ s6,
    float* __restrict__ d0, float* __restrict__ d1, float* __restrict__ d2,
    float* __restrict__ d3, float* __restrict__ d4, float* __restrict__ d5,
    float* __restrict__ d6) {
    const int z = blockIdx.z;
    const float* src; float* dst; int n4;
    switch (z) {
        case 0: src = s0; dst = d0; n4 = M_TOK * SIZE / 4; break;
        case 1: src = s1; dst = d1; n4 = M_TOK * SIZE / 4; break;
        case 2: src = s2; dst = d2; n4 = M_TOK * SIZE / 4; break;
        case 3: src = s3; dst = d3; n4 = SIZE * SIZE / 4; break;
        case 4: src = s4; dst = d4; n4 = SIZE * SIZE / 4; break;
        case 5: src = s5; dst = d5; n4 = SIZE * SIZE / 4; break;
        default: src = s6; dst = d6; n4 = SIZE * SIZE / 4; break;
    }
    int stride = gridDim.x * 256;
    for (int i = blockIdx.x * 256 + threadIdx.x; i < n4; i += stride) {
        float4 t = reinterpret_cast<const float4*>(src)[i];
        reinterpret_cast<float4*>(dst)[i] =
            make_float4(f2tf32f(t.x), f2tf32f(t.y), f2tf32f(t.z), f2tf32f(t.w));
    }
}

// ==================================================================
// 4-warp GEMM core (cp.async double-buffered): CTA 128x128, warp 64x64.
// ==================================================================
template<int IN_MODE, int OUT_MODE>
__device__ __forceinline__ void gemm_core(const float* __restrict__ X,
                                          const float* __restrict__ W,
                                          const float* __restrict__ bias,
                                          float* __restrict__ Y,
                                          int bm, int bn, float* smem) {
    float* As = smem;
    float* Bs = As + 2 * 128 * LDA;
    float* stage = Bs + 2 * 128 * LDA;

    const int tid = threadIdx.x, wid = tid >> 5, lane = tid & 31;
    const int wm0 = (wid & 1) * 64, wn0 = (wid >> 1) * 64;

    FragC acc[4][4];
    #pragma unroll
    for (int mt = 0; mt < 4; mt++)
        #pragma unroll
        for (int nt = 0; nt < 4; nt++) wmma::fill_fragment(acc[mt][nt], 0.0f);

    auto xsrc = [&](int kc, int i, int j) -> const float* {
        if (IN_MODE == 0) {
            return X + (size_t)(bm * 128 + i) * 1024 + kc + j;
        } else {
            int gm = bm * 128 + i;
            int b = gm >> 11, s = gm & 2047;
            int h = kc >> 6, d0 = (kc & 63) + j;
            return X + ((((size_t)b * HEADS + h) * SEQ + s) << 6) + d0;
        }
    };

    auto issue_chunk = [&](int kc, float* Ad, float* Bd) {
        #pragma unroll
        for (int l = 0; l < 8; l++) {
            int v = tid + l * 128;
            int i = v >> 3, j = (v & 7) * 4;
            cpa16(&Ad[i * LDA + j], xsrc(kc, i, j));
            cpa16(&Bd[i * LDA + j], W + (size_t)(bn * 128 + i) * 1024 + kc + j);
        }
        cpa_commit();
    };

    issue_chunk(0, As, Bs);

    for (int c = 0; c < 32; c++) {
        const int buf = c & 1;
        const bool nxt = (c + 1 < 32);
        if (nxt) {
            issue_chunk((c + 1) * 32, As + (buf ^ 1) * 128 * LDA,
                        Bs + (buf ^ 1) * 128 * LDA);
            cpa_wait<1>();
        } else {
            cpa_wait<0>();
        }
        __syncthreads();

        const float* Ab = As + buf * 128 * LDA;
        const float* Bb = Bs + buf * 128 * LDA;
        #pragma unroll
        for (int ks = 0; ks < 32; ks += 8) {
            FragA af[4];
            FragBc bf[4];
            #pragma unroll
            for (int mt = 0; mt < 4; mt++)
                wmma::load_matrix_sync(af[mt], &Ab[(wm0 + mt * 16) * LDA + ks], LDA);
            #pragma unroll
            for (int nt = 0; nt < 4; nt++)
                wmma::load_matrix_sync(bf[nt], &Bb[(wn0 + nt * 16) * LDA + ks], LDA);
            #pragma unroll
            for (int mt = 0; mt < 4; mt++)
                #pragma unroll
                for (int nt = 0; nt < 4; nt++)
                    wmma::mma_sync(acc[mt][nt], af[mt], bf[nt], acc[mt][nt]);
        }
        __syncthreads();
    }

    float* st = stage + wid * 272;
    #pragma unroll
    for (int mt = 0; mt < 4; mt++) {
        #pragma unroll
        for (int nt = 0; nt < 4; nt++) {
            wmma::store_matrix_sync(st, acc[mt][nt], 16, wmma::mem_row_major);
            __syncwarp();
            int r = lane >> 1, c8 = (lane & 1) * 8;
            int gm = bm * 128 + wm0 + mt * 16 + r;
            int gn_t = bn * 128 + wn0 + nt * 16;
            float out[8];
            #pragma unroll
            for (int jj = 0; jj < 8; jj++) {
                float vv = st[r * 16 + c8 + jj] + bias[gn_t + c8 + jj];
                out[jj] = (OUT_MODE == 1) ? f2tf32f(vv) : vv;
            }
            float* dst;
            if (OUT_MODE == 0) {
                dst = Y + (size_t)gm * SIZE + gn_t + c8;
            } else {
                int b = gm >> 11, s = gm & 2047;
                int h = gn_t >> 6, d0 = (gn_t & 63) + c8;
                dst = Y + ((((size_t)b * HEADS + h) * SEQ + s) << 6) + d0;
            }
            *reinterpret_cast<float4*>(dst)     = make_float4(out[0], out[1], out[2], out[3]);
            *reinterpret_cast<float4*>(dst + 4) = make_float4(out[4], out[5], out[6], out[7]);
            __syncwarp();
        }
    }
}

__global__ void __launch_bounds__(128, 2) proj3_wmma(
    const float* __restrict__ X0, const float* __restrict__ X1, const float* __restrict__ X2,
    const float* __restrict__ W0, const float* __restrict__ W1, const float* __restrict__ W2,
    const float* __restrict__ b0, const float* __restrict__ b1, const float* __restrict__ b2,
    float* __restrict__ Y0, float* __restrict__ Y1, float* __restrict__ Y2) {
    extern __shared__ __align__(16) float smem[];
    const int z = blockIdx.z;
    const float* X = (z == 0) ? X0 : (z == 1) ? X1 : X2;
    const float* W = (z == 0) ? W0 : (z == 1) ? W1 : W2;
    const float* bias = (z == 0) ? b0 : (z == 1) ? b1 : b2;
    float* Y = (z == 0) ? Y0 : (z == 1) ? Y1 : Y2;
    gemm_core<0, 1>(X, W, bias, Y, blockIdx.y, blockIdx.x, smem);
}

__global__ void __launch_bounds__(128, 2) outproj_wmma(const float* __restrict__ Xh,
                                                       const float* __restrict__ W,
                                                       const float* __restrict__ bias,
                                                       float* __restrict__ Y) {
    extern __shared__ __align__(16) float smem[];
    gemm_core<1, 0>(Xh, W, bias, Y, blockIdx.y, blockIdx.x, smem);
}

// ==================================================================
// scores_exp: E = exp((Q.K^T)/8) with causal mask; single smem load.
// Upper-tri CTAs write zeros. Row partial sums -> g_psum.
// ==================================================================
__global__ void __launch_bounds__(256, 2) scores_exp(const float* __restrict__ Q,
                                                     const float* __restrict__ Kh,
                                                     float* __restrict__ attn,
                                                     float* __restrict__ psum) {
    const int bn = blockIdx.x, bm = blockIdx.y, bh = blockIdx.z;
    const int tid = threadIdx.x;

    if (bn > bm) {
        const float4 z4 = {0.f, 0.f, 0.f, 0.f};
        float* base = attn + ((size_t)bh * SEQ + bm * 128) * SEQ + bn * 128;
        #pragma unroll
        for (int l = 0; l < 16; l++) {
            int idx = tid + l * 256;
            int i = idx >> 5, j4 = idx & 31;
            *reinterpret_cast<float4*>(base + (size_t)i * SEQ + j4 * 4) = z4;
        }
        return;
    }

    extern __shared__ __align__(16) float smem[];
    float* Qs = smem;                      // 128*LDQ
    float* Ks = Qs + 128 * LDQ;            // 128*LDQ
    float* stage = Ks + 128 * LDQ;         // 8*272
    float* psums_sm = stage + 8 * 272;     // 128*4

    const int wid = tid >> 5, lane = tid & 31;
    const int wm0 = (wid & 1) * 64, wng = wid >> 1;
    const int wn0 = wng * 32;
    const float* q = Q + (size_t)bh * SEQ * HDIM;
    const float* k = Kh + (size_t)bh * SEQ * HDIM;
    const bool diag = (bm == bn);

    #pragma unroll
    for (int l = 0; l < 8; l++) {
        int f4 = tid + l * 256;
        int i = f4 >> 4, j = (f4 & 15) * 4;
        cpa16(&Qs[i * LDQ + j], q + (size_t)(bm * 128 + i) * HDIM + j);
        cpa16(&Ks[i * LDQ + j], k + (size_t)(bn * 128 + i) * HDIM + j);
    }
    cpa_commit();
    cpa_wait<0>();
    __syncthreads();

    FragC acc[4][2];
    #pragma unroll
    for (int mt = 0; mt < 4; mt++)
        #pragma unroll
        for (int nt = 0; nt < 2; nt++) wmma::fill_fragment(acc[mt][nt], 0.0f);

    #pragma unroll
    for (int ks = 0; ks < 64; ks += 8) {
        FragA af[4];
        FragBc bf[2];
        #pragma unroll
        for (int mt = 0; mt < 4; mt++)
            wmma::load_matrix_sync(af[mt], &Qs[(wm0 + mt * 16) * LDQ + ks], LDQ);
        #pragma unroll
        for (int nt = 0; nt < 2; nt++)
            wmma::load_matrix_sync(bf[nt], &Ks[(wn0 + nt * 16) * LDQ + ks], LDQ);
        #pragma unroll
        for (int mt = 0; mt < 4; mt++)
            #pragma unroll
            for (int nt = 0; nt < 2; nt++)
                wmma::mma_sync(acc[mt][nt], af[mt], bf[nt], acc[mt][nt]);
    }

    float* st = stage + wid * 272;
    #pragma unroll
    for (int mt = 0; mt < 4; mt++) {
        float rowsum = 0.f;
        #pragma unroll
        for (int nt = 0; nt < 2; nt++) {
            wmma::store_matrix_sync(st, acc[mt][nt], 16, wmma::mem_row_major);
            __syncwarp();
            int r = lane >> 1, c8 = (lane & 1) * 8;
            int gq = bm * 128 + wm0 + mt * 16 + r;
            int gk0 = bn * 128 + wn0 + nt * 16 + c8;
            float e[8];
            #pragma unroll
            for (int jj = 0; jj < 8; jj++) {
                float s = st[r * 16 + c8 + jj] * 0.125f;
                float v = __expf(s);
                if (diag && (gk0 + jj > gq)) v = 0.f;
                e[jj] = v;
                rowsum += v;
            }
            float* dst = attn + ((size_t)bh * SEQ + gq) * SEQ + gk0;
            *reinterpret_cast<float4*>(dst)     = make_float4(e[0], e[1], e[2], e[3]);
            *reinterpret_cast<float4*>(dst + 4) = make_float4(e[4], e[5], e[6], e[7]);
            __syncwarp();
        }
        rowsum += __shfl_xor_sync(~0u, rowsum, 1);
        if ((lane & 1) == 0)
            psums_sm[(wm0 + mt * 16 + (lane >> 1)) * 4 + wng] = rowsum;
    }
    __syncthreads();
    if (tid < 128) {
        float s = psums_sm[tid * 4 + 0] + psums_sm[tid * 4 + 1]
                + psums_sm[tid * 4 + 2] + psums_sm[tid * 4 + 3];
        psum[((size_t)(bh * NQT + bm) * 128 + tid) * NQT + bn] = s;
    }
}

// ==================================================================
// attnv_v2: per (qt, bh) CTA 128q x 64d, 128 threads, 3 CTAs/SM.
//  - cp.async E (raw) + V into smem (2-stage)
//  - MMA on raw E (HW tf32 truncation), O scaled by il in epilogue
//  - P = E*il written gmem from smem, decoupled from the MMA stream
// ==================================================================
__global__ void __launch_bounds__(128, 3) attnv_v2(float* __restrict__ attn,
                                                   const float* __restrict__ V,
                                                   const float* __restrict__ psum,
                                                   float* __restrict__ Oh) {
    const int qt = (NQT - 1) - blockIdx.x;   // big tiles first
    const int bh = blockIdx.y;
    extern __shared__ __align__(16) float smem[];
    float* As = smem;                        // 2 * 128*LDA
    float* Vs = As + 2 * 128 * LDA;          // 2 * 32*LDV
    float* stage = Vs + 2 * 32 * LDV;        // 4*272
    float* ilrow = stage + 4 * 272;          // 128

    const int tid = threadIdx.x, wid = tid >> 5, lane = tid & 31;
    const int wm0 = (wid & 1) * 64, wn0 = (wid >> 1) * 32;
    float* a = attn + ((size_t)bh * SEQ + qt * 128) * SEQ;
    const float* v = V + (size_t)bh * SEQ * HDIM;

    // 1/rowsum (128 threads cover the 128 rows)
    {
        const float* ps = psum + ((size_t)(bh * NQT + qt) * 128 + tid) * NQT;
        float s = 0.f;
        for (int t = 0; t <= qt; t++) s += ps[t];
        ilrow[tid] = 1.0f / s;
    }

    FragC acc[4][2];
    #pragma unroll
    for (int mt = 0; mt < 4; mt++)
        #pragma unroll
        for (int nt = 0; nt < 2; nt++) wmma::fill_fragment(acc[mt][nt], 0.0f);

    const int NCH = (qt + 1) * 4;            // 32-col chunks

    auto issue = [&](int c) {
        const int kc = c * 32;
        float* Ad = As + (c & 1) * 128 * LDA;
        float* Vd = Vs + (c & 1) * 32 * LDV;
        #pragma unroll
        for (int l = 0; l < 8; l++) {
            int idx = tid + l * 128;         // 0..1023
            int i = idx >> 3, j = (idx & 7) * 4;
            cpa16(&Ad[i * LDA + j], a + (size_t)i * SEQ + kc + j);
        }
        #pragma unroll
        for (int l = 0; l < 4; l++) {
            int idx = tid + l * 128;         // 0..511
            int i = idx >> 4, j = (idx & 15) * 4;
            cpa16(&Vd[i * LDV + j], v + (size_t)(kc + i) * HDIM + j);
        }
        cpa_commit();
    };

    issue(0);

    for (int c = 0; c < NCH; c++) {
        const int buf = c & 1;
        const bool nxt = (c + 1 < NCH);
        if (nxt) {
            issue(c + 1);
            cpa_wait<1>();
        } else {
            cpa_wait<0>();
        }
        __syncthreads();   // chunk c visible; also orders ilrow init (c==0)

        const float* Ab = As + buf * 128 * LDA;
        const float* Vb = Vs + buf * 32 * LDV;
        #pragma unroll
        for (int ks = 0; ks < 32; ks += 8) {
            FragA af[4];
            FragBr bf[2];
            #pragma unroll
            for (int mt = 0; mt < 4; mt++)
                wmma::load_matrix_sync(af[mt], &Ab[(wm0 + mt * 16) * LDA + ks], LDA);
            #pragma unroll
            for (int nt = 0; nt < 2; nt++)
                wmma::load_matrix_sync(bf[nt], &Vb[ks * LDV + wn0 + nt * 16], LDV);
            #pragma unroll
            for (int mt = 0; mt < 4; mt++)
                #pragma unroll
                for (int nt = 0; nt < 2; nt++)
                    wmma::mma_sync(acc[mt][nt], af[mt], bf[nt], acc[mt][nt]);
        }

        // P = E * il, streamed smem -> gmem (parallel to tensor work above)
        {
            const int kc = c * 32;
            #pragma unroll
            for (int l = 0; l < 8; l++) {
                int idx = tid + l * 128;
                int i = idx >> 3, j = (idx & 7) * 4;
                float4 t = *reinterpret_cast<const float4*>(&Ab[i * LDA + j]);
                float il = ilrow[i];
                t.x *= il; t.y *= il; t.z *= il; t.w *= il;
                *reinterpret_cast<float4*>(a + (size_t)i * SEQ + kc + j) = t;
            }
        }
        __syncthreads();   // readers done before next issue overwrites buf
    }

    // epilogue: O = il * acc, tf32-rounded, to Oh head layout
    float* st = stage + wid * 272;
    #pragma unroll
    for (int mt = 0; mt < 4; mt++) {
        #pragma unroll
        for (int nt = 0; nt < 2; nt++) {
            wmma::store_matrix_sync(st, acc[mt][nt], 16, wmma::mem_row_major);
            __syncwarp();
            int r = lane >> 1, c8 = (lane & 1) * 8;
            int rloc = wm0 + mt * 16 + r;
            int gq = qt * 128 + rloc;
            int d0 = wn0 + nt * 16 + c8;
            float il = ilrow[rloc];
            float out[8];
            #pragma unroll
            for (int jj = 0; jj < 8; jj++)
                out[jj] = f2tf32f(st[r * 16 + c8 + jj] * il);
            float* dst = Oh + (((size_t)bh * SEQ + gq) << 6) + d0;
            *reinterpret_cast<float4*>(dst)     = make_float4(out[0], out[1], out[2], out[3]);
            *reinterpret_cast<float4*>(dst + 4) = make_float4(out[4], out[5], out[6], out[7]);
            __syncwarp();
        }
    }
}

// ==================================================================
// host launcher
// ==================================================================
extern "C" void kernel_launch(void* const* d_in, const int* in_sizes, int n_in,
                              void* d_out, int out_size) {
    const float* key   = (const float*)d_in[0];
    const float* value = (const float*)d_in[1];
    const float* query = (const float*)d_in[2];
    const float* Wk = (const float*)d_in[4];
    const float* bk = (const float*)d_in[5];
    const float* Wv = (const float*)d_in[6];
    const float* bv = (const float*)d_in[7];
    const float* Wq = (const float*)d_in[8];
    const float* bq = (const float*)d_in[9];
    const float* Wo = (const float*)d_in[10];
    const float* bo = (const float*)d_in[11];

    float *qh, *kh, *vh, *oh, *psum, *attn_scr, *out_scr;
    float *cq, *ck, *cv, *cwq, *cwk, *cwv, *cwo;
    cudaGetSymbolAddress((void**)&qh, g_q);
    cudaGetSymbolAddress((void**)&kh, g_k);
    cudaGetSymbolAddress((void**)&vh, g_v);
    cudaGetSymbolAddress((void**)&oh, g_oh);
    cudaGetSymbolAddress((void**)&psum, g_psum);
    cudaGetSymbolAddress((void**)&attn_scr, g_attn_scratch);
    cudaGetSymbolAddress((void**)&out_scr, g_out_scratch);
    cudaGetSymbolAddress((void**)&cq, g_cq);
    cudaGetSymbolAddress((void**)&ck, g_ck);
    cudaGetSymbolAddress((void**)&cv, g_cv);
    cudaGetSymbolAddress((void**)&cwq, g_cwq);
    cudaGetSymbolAddress((void**)&cwk, g_cwk);
    cudaGetSymbolAddress((void**)&cwv, g_cwv);
    cudaGetSymbolAddress((void**)&cwo, g_cwo);

    const long long OUT_ELE  = (long long)M_TOK * SIZE;
    const long long ATTN_ELE = (long long)BH * SEQ * SEQ;

    float* dout = (float*)d_out;
    float* outp;
    float* attnp;
    if ((long long)out_size >= OUT_ELE + ATTN_ELE) {
        outp = dout; attnp = dout + OUT_ELE;
    } else if ((long long)out_size == ATTN_ELE) {
        attnp = dout; outp = out_scr;
    } else {
        outp = dout; attnp = attn_scr;
    }

    cudaFuncSetAttribute(proj3_wmma,   cudaFuncAttributeMaxDynamicSharedMemorySize, SMEM_GEMM);
    cudaFuncSetAttribute(outproj_wmma, cudaFuncAttributeMaxDynamicSharedMemorySize, SMEM_GEMM);
    cudaFuncSetAttribute(scores_exp,   cudaFuncAttributeMaxDynamicSharedMemorySize, SMEM_SCORES);
    cudaFuncSetAttribute(attnv_v2,     cudaFuncAttributeMaxDynamicSharedMemorySize, SMEM_AV2);

    dim3 thrG(128);
    dim3 thr(256);

    // 0) round inputs + weights to tf32 once
    dim3 gCvt(512, 1, 7);
    cvt7_tf32<<<gCvt, thr>>>(query, key, value, Wq, Wk, Wv, Wo,
                             cq, ck, cv, cwq, cwk, cwv, cwo);

    // 1) projections
    dim3 gProj3(SIZE / 128, M_TOK / 128, 3);        // (8, 32, 3)
    proj3_wmma<<<gProj3, thrG, SMEM_GEMM>>>(cq, ck, cv,
                                            cwq, cwk, cwv,
                                            bq, bk, bv,
                                            qh, kh, vh);

    // 2) scores + exp + psum (writes E and upper-tri zeros)
    dim3 gScores(NQT, NQT, BH);                     // (16, 16, 32)
    scores_exp<<<gScores, thr, SMEM_SCORES>>>(qh, kh, attnp, psum);

    // 3) normalize (P write) + O = P @ V
    dim3 gAV(NQT, BH);                              // (16, 32)
    attnv_v2<<<gAV, thrG, SMEM_AV2>>>(attnp, vh, psum, oh);

    // 4) output projection
    dim3 gOut(SIZE / 128, M_TOK / 128);             // (8, 32)
    outproj_wmma<<<gOut, thrG, SMEM_GEMM>>>(oh, cwo, bo, outp);
}

// round 16
// speedup vs baseline: 1.1954x; 1.0160x over previous
#include <cuda_runtime.h>
#include <mma.h>
#include <cstdint>
#include <math.h>

using namespace nvcuda;

// Problem constants
#define BATCH 2
#define SEQ   2048
#define SIZE  1024
#define HEADS 16
#define HDIM  64
#define M_TOK (BATCH * SEQ)
#define BH    (BATCH * HEADS)
#define NQT   (SEQ / 128)     // 16 score q-tiles
#define NQT64 (SEQ / 64)      // 32 attnv q-tiles

// -------- scratch (device globals; no allocations allowed) --------
__device__ float g_q[(size_t)BH * SEQ * HDIM];        // [bh, s, d] (tf32-rounded)
__device__ float g_k[(size_t)BH * SEQ * HDIM];
__device__ float g_v[(size_t)BH * SEQ * HDIM];
__device__ float g_oh[(size_t)BH * SEQ * HDIM];       // (tf32-rounded)
__device__ float g_psum[(size_t)BH * SEQ * NQT];
__device__ float g_attn_scratch[(size_t)BH * SEQ * SEQ];
__device__ float g_out_scratch[(size_t)M_TOK * SIZE];
// tf32-rounded copies of harness inputs
__device__ float g_cq[(size_t)M_TOK * SIZE];
__device__ float g_ck[(size_t)M_TOK * SIZE];
__device__ float g_cv[(size_t)M_TOK * SIZE];
__device__ float g_cwq[(size_t)SIZE * SIZE];
__device__ float g_cwk[(size_t)SIZE * SIZE];
__device__ float g_cwv[(size_t)SIZE * SIZE];
__device__ float g_cwo[(size_t)SIZE * SIZE];

__device__ __forceinline__ float f2tf32f(float x) {
    uint32_t r;
    asm("cvt.rna.tf32.f32 %0, %1;" : "=r"(r) : "f"(x));
    return __uint_as_float(r);
}
__device__ __forceinline__ uint32_t smem_u32(const void* p) {
    uint32_t a;
    asm("{ .reg .u64 t; cvta.to.shared.u64 t, %1; cvt.u32.u64 %0, t; }" : "=r"(a) : "l"(p));
    return a;
}
__device__ __forceinline__ void cpa16(float* smem_dst, const float* gsrc) {
    uint32_t d = smem_u32(smem_dst);
    asm volatile("cp.async.cg.shared.global [%0], [%1], 16;" :: "r"(d), "l"(gsrc));
}
__device__ __forceinline__ void cpa_commit() {
    asm volatile("cp.async.commit_group;");
}
template<int N>
__device__ __forceinline__ void cpa_wait() {
    asm volatile("cp.async.wait_group %0;" :: "n"(N));
}

typedef wmma::fragment<wmma::matrix_a, 16, 16, 8, wmma::precision::tf32, wmma::row_major> FragA;
typedef wmma::fragment<wmma::matrix_b, 16, 16, 8, wmma::precision::tf32, wmma::col_major> FragBc;
typedef wmma::fragment<wmma::matrix_b, 16, 16, 8, wmma::precision::tf32, wmma::row_major> FragBr;
typedef wmma::fragment<wmma::accumulator, 16, 16, 8, float> FragC;

#define LDA 36   // smem leading dim for 32-wide K tiles (pad 4)
#define LDQ 68   // smem leading dim for 64-wide tiles (pad 4)
#define LDV 68

// dynamic smem sizes (bytes)
#define SMEM_GEMM   ((2*128*LDA*2 + 4*272) * 4)                   // 78080
#define SMEM_SCORES ((2*128*LDQ + 8*272 + 128*4) * 4)             // 80384
#define SMEM_AV3    ((2*64*LDA + 2*32*LDV + 4*272 + 64) * 4)      // 40448

// ==================================================================
// cvt7: round 7 arrays to tf32-in-fp32 (z selects array).
// ==================================================================
__global__ void __launch_bounds__(256) cvt7_tf32(
    const float* __restrict__ s0, const float* __restrict__ s1, const float* __restrict__ s2,
    const float* __restrict__ s3, const float* __restrict__ s4, const float* __restrict__ s5,
    const float* __restrict__ s6,
    float* __restrict__ d0, float* __restrict__ d1, float* __restrict__ d2,
    float* __restrict__ d3, float* __restrict__ d4, float* __restrict__ d5,
    float* __restrict__ d6) {
    const int z = blockIdx.z;
    const float* src; float* dst; int n4;
    switch (z) {
        case 0: src = s0; dst = d0; n4 = M_TOK * SIZE / 4; break;
        case 1: src = s1; dst = d1; n4 = M_TOK * SIZE / 4; break;
        case 2: src = s2; dst = d2; n4 = M_TOK * SIZE / 4; break;
        case 3: src = s3; dst = d3; n4 = SIZE * SIZE / 4; break;
        case 4: src = s4; dst = d4; n4 = SIZE * SIZE / 4; break;
        case 5: src = s5; dst = d5; n4 = SIZE * SIZE / 4; break;
        default: src = s6; dst = d6; n4 = SIZE * SIZE / 4; break;
    }
    int stride = gridDim.x * 256;
    for (int i = blockIdx.x * 256 + threadIdx.x; i < n4; i += stride) {
        float4 t = reinterpret_cast<const float4*>(src)[i];
        reinterpret_cast<float4*>(dst)[i] =
            make_float4(f2tf32f(t.x), f2tf32f(t.y), f2tf32f(t.z), f2tf32f(t.w));
    }
}

// ==================================================================
// 4-warp GEMM core: CTA 128x128, warp 64x64, cp.async double-buffered
// smem + software-pipelined fragment double buffering.
// ==================================================================
template<int IN_MODE, int OUT_MODE>
__device__ __forceinline__ void gemm_core(const float* __restrict__ X,
                                          const float* __restrict__ W,
                                          const float* __restrict__ bias,
                                          float* __restrict__ Y,
                                          int bm, int bn, float* smem) {
    float* As = smem;
    float* Bs = As + 2 * 128 * LDA;
    float* stage = Bs + 2 * 128 * LDA;

    const int tid = threadIdx.x, wid = tid >> 5, lane = tid & 31;
    const int wm0 = (wid & 1) * 64, wn0 = (wid >> 1) * 64;

    FragC acc[4][4];
    #pragma unroll
    for (int mt = 0; mt < 4; mt++)
        #pragma unroll
        for (int nt = 0; nt < 4; nt++) wmma::fill_fragment(acc[mt][nt], 0.0f);

    auto xsrc = [&](int kc, int i, int j) -> const float* {
        if (IN_MODE == 0) {
            return X + (size_t)(bm * 128 + i) * 1024 + kc + j;
        } else {
            int gm = bm * 128 + i;
            int b = gm >> 11, s = gm & 2047;
            int h = kc >> 6, d0 = (kc & 63) + j;
            return X + ((((size_t)b * HEADS + h) * SEQ + s) << 6) + d0;
        }
    };

    auto issue_chunk = [&](int kc, float* Ad, float* Bd) {
        #pragma unroll
        for (int l = 0; l < 8; l++) {
            int v = tid + l * 128;
            int i = v >> 3, j = (v & 7) * 4;
            cpa16(&Ad[i * LDA + j], xsrc(kc, i, j));
            cpa16(&Bd[i * LDA + j], W + (size_t)(bn * 128 + i) * 1024 + kc + j);
        }
        cpa_commit();
    };

    issue_chunk(0, As, Bs);

    for (int c = 0; c < 32; c++) {
        const int buf = c & 1;
        const bool nxt = (c + 1 < 32);
        if (nxt) {
            issue_chunk((c + 1) * 32, As + (buf ^ 1) * 128 * LDA,
                        Bs + (buf ^ 1) * 128 * LDA);
            cpa_wait<1>();
        } else {
            cpa_wait<0>();
        }
        __syncthreads();

        const float* Ab = As + buf * 128 * LDA;
        const float* Bb = Bs + buf * 128 * LDA;

        // fragment double-buffered ks loop (4 steps of 8)
        FragA af[2][4];
        FragBc bf[2][4];
        #pragma unroll
        for (int mt = 0; mt < 4; mt++)
            wmma::load_matrix_sync(af[0][mt], &Ab[(wm0 + mt * 16) * LDA + 0], LDA);
        #pragma unroll
        for (int nt = 0; nt < 4; nt++)
            wmma::load_matrix_sync(bf[0][nt], &Bb[(wn0 + nt * 16) * LDA + 0], LDA);
        #pragma unroll
        for (int s8 = 0; s8 < 4; s8++) {
            const int cur = s8 & 1;
            if (s8 < 3) {
                const int ksn = (s8 + 1) * 8;
                #pragma unroll
                for (int mt = 0; mt < 4; mt++)
                    wmma::load_matrix_sync(af[cur ^ 1][mt], &Ab[(wm0 + mt * 16) * LDA + ksn], LDA);
                #pragma unroll
                for (int nt = 0; nt < 4; nt++)
                    wmma::load_matrix_sync(bf[cur ^ 1][nt], &Bb[(wn0 + nt * 16) * LDA + ksn], LDA);
            }
            #pragma unroll
            for (int mt = 0; mt < 4; mt++)
                #pragma unroll
                for (int nt = 0; nt < 4; nt++)
                    wmma::mma_sync(acc[mt][nt], af[cur][mt], bf[cur][nt], acc[mt][nt]);
        }
        __syncthreads();
    }

    float* st = stage + wid * 272;
    #pragma unroll
    for (int mt = 0; mt < 4; mt++) {
        #pragma unroll
        for (int nt = 0; nt < 4; nt++) {
            wmma::store_matrix_sync(st, acc[mt][nt], 16, wmma::mem_row_major);
            __syncwarp();
            int r = lane >> 1, c8 = (lane & 1) * 8;
            int gm = bm * 128 + wm0 + mt * 16 + r;
            int gn_t = bn * 128 + wn0 + nt * 16;
            float out[8];
            #pragma unroll
            for (int jj = 0; jj < 8; jj++) {
                float vv = st[r * 16 + c8 + jj] + bias[gn_t + c8 + jj];
                out[jj] = (OUT_MODE == 1) ? f2tf32f(vv) : vv;
            }
            float* dst;
            if (OUT_MODE == 0) {
                dst = Y + (size_t)gm * SIZE + gn_t + c8;
            } else {
                int b = gm >> 11, s = gm & 2047;
                int h = gn_t >> 6, d0 = (gn_t & 63) + c8;
                dst = Y + ((((size_t)b * HEADS + h) * SEQ + s) << 6) + d0;
            }
            *reinterpret_cast<float4*>(dst)     = make_float4(out[0], out[1], out[2], out[3]);
            *reinterpret_cast<float4*>(dst + 4) = make_float4(out[4], out[5], out[6], out[7]);
            __syncwarp();
        }
    }
}

__global__ void __launch_bounds__(128, 2) proj3_wmma(
    const float* __restrict__ X0, const float* __restrict__ X1, const float* __restrict__ X2,
    const float* __restrict__ W0, const float* __restrict__ W1, const float* __restrict__ W2,
    const float* __restrict__ b0, const float* __restrict__ b1, const float* __restrict__ b2,
    float* __restrict__ Y0, float* __restrict__ Y1, float* __restrict__ Y2) {
    extern __shared__ __align__(16) float smem[];
    const int z = blockIdx.z;
    const float* X = (z == 0) ? X0 : (z == 1) ? X1 : X2;
    const float* W = (z == 0) ? W0 : (z == 1) ? W1 : W2;
    const float* bias = (z == 0) ? b0 : (z == 1) ? b1 : b2;
    float* Y = (z == 0) ? Y0 : (z == 1) ? Y1 : Y2;
    gemm_core<0, 1>(X, W, bias, Y, blockIdx.y, blockIdx.x, smem);
}

__global__ void __launch_bounds__(128, 2) outproj_wmma(const float* __restrict__ Xh,
                                                       const float* __restrict__ W,
                                                       const float* __restrict__ bias,
                                                       float* __restrict__ Y) {
    extern __shared__ __align__(16) float smem[];
    gemm_core<1, 0>(Xh, W, bias, Y, blockIdx.y, blockIdx.x, smem);
}

// ==================================================================
// scores_exp: E = exp((Q.K^T)/8) with causal mask; single smem load.
// Upper-tri CTAs write zeros. Row partial sums -> g_psum.
// ==================================================================
__global__ void __launch_bounds__(256, 2) scores_exp(const float* __restrict__ Q,
                                                     const float* __restrict__ Kh,
                                                     float* __restrict__ attn,
                                                     float* __restrict__ psum) {
    const int bn = blockIdx.x, bm = blockIdx.y, bh = blockIdx.z;
    const int tid = threadIdx.x;

    if (bn > bm) {
        const float4 z4 = {0.f, 0.f, 0.f, 0.f};
        float* base = attn + ((size_t)bh * SEQ + bm * 128) * SEQ + bn * 128;
        #pragma unroll
        for (int l = 0; l < 16; l++) {
            int idx = tid + l * 256;
            int i = idx >> 5, j4 = idx & 31;
            *reinterpret_cast<float4*>(base + (size_t)i * SEQ + j4 * 4) = z4;
        }
        return;
    }

    extern __shared__ __align__(16) float smem[];
    float* Qs = smem;                      // 128*LDQ
    float* Ks = Qs + 128 * LDQ;            // 128*LDQ
    float* stage = Ks + 128 * LDQ;         // 8*272
    float* psums_sm = stage + 8 * 272;     // 128*4

    const int wid = tid >> 5, lane = tid & 31;
    const int wm0 = (wid & 1) * 64, wng = wid >> 1;
    const int wn0 = wng * 32;
    const float* q = Q + (size_t)bh * SEQ * HDIM;
    const float* k = Kh + (size_t)bh * SEQ * HDIM;
    const bool diag = (bm == bn);

    #pragma unroll
    for (int l = 0; l < 8; l++) {
        int f4 = tid + l * 256;
        int i = f4 >> 4, j = (f4 & 15) * 4;
        cpa16(&Qs[i * LDQ + j], q + (size_t)(bm * 128 + i) * HDIM + j);
        cpa16(&Ks[i * LDQ + j], k + (size_t)(bn * 128 + i) * HDIM + j);
    }
    cpa_commit();
    cpa_wait<0>();
    __syncthreads();

    FragC acc[4][2];
    #pragma unroll
    for (int mt = 0; mt < 4; mt++)
        #pragma unroll
        for (int nt = 0; nt < 2; nt++) wmma::fill_fragment(acc[mt][nt], 0.0f);

    #pragma unroll
    for (int ks = 0; ks < 64; ks += 8) {
        FragA af[4];
        FragBc bf[2];
        #pragma unroll
        for (int mt = 0; mt < 4; mt++)
            wmma::load_matrix_sync(af[mt], &Qs[(wm0 + mt * 16) * LDQ + ks], LDQ);
        #pragma unroll
        for (int nt = 0; nt < 2; nt++)
            wmma::load_matrix_sync(bf[nt], &Ks[(wn0 + nt * 16) * LDQ + ks], LDQ);
        #pragma unroll
        for (int mt = 0; mt < 4; mt++)
            #pragma unroll
            for (int nt = 0; nt < 2; nt++)
                wmma::mma_sync(acc[mt][nt], af[mt], bf[nt], acc[mt][nt]);
    }

    float* st = stage + wid * 272;
    #pragma unroll
    for (int mt = 0; mt < 4; mt++) {
        float rowsum = 0.f;
        #pragma unroll
        for (int nt = 0; nt < 2; nt++) {
            wmma::store_matrix_sync(st, acc[mt][nt], 16, wmma::mem_row_major);
            __syncwarp();
            int r = lane >> 1, c8 = (lane & 1) * 8;
            int gq = bm * 128 + wm0 + mt * 16 + r;
            int gk0 = bn * 128 + wn0 + nt * 16 + c8;
            float e[8];
            #pragma unroll
            for (int jj = 0; jj < 8; jj++) {
                float s = st[r * 16 + c8 + jj] * 0.125f;
                float v = __expf(s);
                if (diag && (gk0 + jj > gq)) v = 0.f;
                e[jj] = v;
                rowsum += v;
            }
            float* dst = attn + ((size_t)bh * SEQ + gq) * SEQ + gk0;
            *reinterpret_cast<float4*>(dst)     = make_float4(e[0], e[1], e[2], e[3]);
            *reinterpret_cast<float4*>(dst + 4) = make_float4(e[4], e[5], e[6], e[7]);
            __syncwarp();
        }
        rowsum += __shfl_xor_sync(~0u, rowsum, 1);
        if ((lane & 1) == 0)
            psums_sm[(wm0 + mt * 16 + (lane >> 1)) * 4 + wng] = rowsum;
    }
    __syncthreads();
    if (tid < 128) {
        float s = psums_sm[tid * 4 + 0] + psums_sm[tid * 4 + 1]
                + psums_sm[tid * 4 + 2] + psums_sm[tid * 4 + 3];
        psum[((size_t)(bh * NQT + bm) * 128 + tid) * NQT + bn] = s;
    }
}

// ==================================================================
// attnv_v3: 64-row q-tiles, grid (32, BH), 128 threads, 4 CTAs/SM.
//  - cp.async E (raw) + V, 2-stage; MMA truncates E to tf32
//  - P = E*il streamed out between syncs; O scaled by il in epilogue
//  - columns >= (t+1)*64 are exact zeros from scores_exp (left as-is)
// ==================================================================
__global__ void __launch_bounds__(128, 4) attnv_v3(float* __restrict__ attn,
                                                   const float* __restrict__ V,
                                                   const float* __restrict__ psum,
                                                   float* __restrict__ Oh) {
    const int t = (NQT64 - 1) - blockIdx.x;   // big tiles first
    const int bh = blockIdx.y;
    extern __shared__ __align__(16) float smem[];
    float* As = smem;                        // 2 * 64*LDA
    float* Vs = As + 2 * 64 * LDA;           // 2 * 32*LDV
    float* stage = Vs + 2 * 32 * LDV;        // 4*272
    float* ilrow = stage + 4 * 272;          // 64

    const int tid = threadIdx.x, wid = tid >> 5, lane = tid & 31;
    const int wm0 = (wid & 1) * 32, wn0 = (wid >> 1) * 32;
    float* a = attn + ((size_t)bh * SEQ + t * 64) * SEQ;
    const float* v = V + (size_t)bh * SEQ * HDIM;

    if (tid < 64) {
        int gr = t * 64 + tid;
        int bm = gr >> 7, rloc = gr & 127;
        const float* ps = psum + ((size_t)(bh * NQT + bm) * 128 + rloc) * NQT;
        float s = 0.f;
        for (int u = 0; u <= bm; u++) s += ps[u];
        ilrow[tid] = 1.0f / s;
    }

    FragC acc[2][2];
    #pragma unroll
    for (int mt = 0; mt < 2; mt++)
        #pragma unroll
        for (int nt = 0; nt < 2; nt++) wmma::fill_fragment(acc[mt][nt], 0.0f);

    const int NCH = (t + 1) * 2;             // 32-col chunks, cover k < (t+1)*64

    auto issue = [&](int c) {
        const int kc = c * 32;
        float* Ad = As + (c & 1) * 64 * LDA;
        float* Vd = Vs + (c & 1) * 32 * LDV;
        #pragma unroll
        for (int l = 0; l < 4; l++) {
            int idx = tid + l * 128;         // 0..511
            int i = idx >> 3, j = (idx & 7) * 4;   // rows 0..63
            cpa16(&Ad[i * LDA + j], a + (size_t)i * SEQ + kc + j);
        }
        #pragma unroll
        for (int l = 0; l < 4; l++) {
            int idx = tid + l * 128;         // 0..511
            int i = idx >> 4, j = (idx & 15) * 4;  // k 0..31, d 0..60
            cpa16(&Vd[i * LDV + j], v + (size_t)(kc + i) * HDIM + j);
        }
        cpa_commit();
    };

    issue(0);

    for (int c = 0; c < NCH; c++) {
        const int buf = c & 1;
        const bool nxt = (c + 1 < NCH);
        if (nxt) {
            issue(c + 1);
            cpa_wait<1>();
        } else {
            cpa_wait<0>();
        }
        __syncthreads();   // chunk c visible; orders ilrow (c==0)

        const float* Ab = As + buf * 64 * LDA;
        const float* Vb = Vs + buf * 32 * LDV;
        #pragma unroll
        for (int ks = 0; ks < 32; ks += 8) {
            FragA af[2];
            FragBr bf[2];
            #pragma unroll
            for (int mt = 0; mt < 2; mt++)
                wmma::load_matrix_sync(af[mt], &Ab[(wm0 + mt * 16) * LDA + ks], LDA);
            #pragma unroll
            for (int nt = 0; nt < 2; nt++)
                wmma::load_matrix_sync(bf[nt], &Vb[ks * LDV + wn0 + nt * 16], LDV);
            #pragma unroll
            for (int mt = 0; mt < 2; mt++)
                #pragma unroll
                for (int nt = 0; nt < 2; nt++)
                    wmma::mma_sync(acc[mt][nt], af[mt], bf[nt], acc[mt][nt]);
        }

        // P = E * il, streamed smem -> gmem
        {
            const int kc = c * 32;
            #pragma unroll
            for (int l = 0; l < 4; l++) {
                int idx = tid + l * 128;
                int i = idx >> 3, j = (idx & 7) * 4;
                float4 tt = *reinterpret_cast<const float4*>(&Ab[i * LDA + j]);
                float il = ilrow[i];
                tt.x *= il; tt.y *= il; tt.z *= il; tt.w *= il;
                *reinterpret_cast<float4*>(a + (size_t)i * SEQ + kc + j) = tt;
            }
        }
        __syncthreads();   // readers done before next issue overwrites buf
    }

    // epilogue: O = il * acc, tf32-rounded, to Oh head layout
    float* st = stage + wid * 272;
    #pragma unroll
    for (int mt = 0; mt < 2; mt++) {
        #pragma unroll
        for (int nt = 0; nt < 2; nt++) {
            wmma::store_matrix_sync(st, acc[mt][nt], 16, wmma::mem_row_major);
            __syncwarp();
            int r = lane >> 1, c8 = (lane & 1) * 8;
            int rloc = wm0 + mt * 16 + r;
            int gq = t * 64 + rloc;
            int d0 = wn0 + nt * 16 + c8;
            float il = ilrow[rloc];
            float out[8];
            #pragma unroll
            for (int jj = 0; jj < 8; jj++)
                out[jj] = f2tf32f(st[r * 16 + c8 + jj] * il);
            float* dst = Oh + (((size_t)bh * SEQ + gq) << 6) + d0;
            *reinterpret_cast<float4*>(dst)     = make_float4(out[0], out[1], out[2], out[3]);
            *reinterpret_cast<float4*>(dst + 4) = make_float4(out[4], out[5], out[6], out[7]);
            __syncwarp();
        }
    }
}

// ==================================================================
// host launcher
// ==================================================================
extern "C" void kernel_launch(void* const* d_in, const int* in_sizes, int n_in,
                              void* d_out, int out_size) {
    const float* key   = (const float*)d_in[0];
    const float* value = (const float*)d_in[1];
    const float* query = (const float*)d_in[2];
    const float* Wk = (const float*)d_in[4];
    const float* bk = (const float*)d_in[5];
    const float* Wv = (const float*)d_in[6];
    const float* bv = (const float*)d_in[7];
    const float* Wq = (const float*)d_in[8];
    const float* bq = (const float*)d_in[9];
    const float* Wo = (const float*)d_in[10];
    const float* bo = (const float*)d_in[11];

    float *qh, *kh, *vh, *oh, *psum, *attn_scr, *out_scr;
    float *cq, *ck, *cv, *cwq, *cwk, *cwv, *cwo;
    cudaGetSymbolAddress((void**)&qh, g_q);
    cudaGetSymbolAddress((void**)&kh, g_k);
    cudaGetSymbolAddress((void**)&vh, g_v);
    cudaGetSymbolAddress((void**)&oh, g_oh);
    cudaGetSymbolAddress((void**)&psum, g_psum);
    cudaGetSymbolAddress((void**)&attn_scr, g_attn_scratch);
    cudaGetSymbolAddress((void**)&out_scr, g_out_scratch);
    cudaGetSymbolAddress((void**)&cq, g_cq);
    cudaGetSymbolAddress((void**)&ck, g_ck);
    cudaGetSymbolAddress((void**)&cv, g_cv);
    cudaGetSymbolAddress((void**)&cwq, g_cwq);
    cudaGetSymbolAddress((void**)&cwk, g_cwk);
    cudaGetSymbolAddress((void**)&cwv, g_cwv);
    cudaGetSymbolAddress((void**)&cwo, g_cwo);

    const long long OUT_ELE  = (long long)M_TOK * SIZE;
    const long long ATTN_ELE = (long long)BH * SEQ * SEQ;

    float* dout = (float*)d_out;
    float* outp;
    float* attnp;
    if ((long long)out_size >= OUT_ELE + ATTN_ELE) {
        outp = dout; attnp = dout + OUT_ELE;
    } else if ((long long)out_size == ATTN_ELE) {
        attnp = dout; outp = out_scr;
    } else {
        outp = dout; attnp = attn_scr;
    }

    cudaFuncSetAttribute(proj3_wmma,   cudaFuncAttributeMaxDynamicSharedMemorySize, SMEM_GEMM);
    cudaFuncSetAttribute(outproj_wmma, cudaFuncAttributeMaxDynamicSharedMemorySize, SMEM_GEMM);
    cudaFuncSetAttribute(scores_exp,   cudaFuncAttributeMaxDynamicSharedMemorySize, SMEM_SCORES);
    cudaFuncSetAttribute(attnv_v3,     cudaFuncAttributeMaxDynamicSharedMemorySize, SMEM_AV3);

    dim3 thrG(128);
    dim3 thr(256);

    // 0) round inputs + weights to tf32 once
    dim3 gCvt(512, 1, 7);
    cvt7_tf32<<<gCvt, thr>>>(query, key, value, Wq, Wk, Wv, Wo,
                             cq, ck, cv, cwq, cwk, cwv, cwo);

    // 1) projections
    dim3 gProj3(SIZE / 128, M_TOK / 128, 3);        // (8, 32, 3)
    proj3_wmma<<<gProj3, thrG, SMEM_GEMM>>>(cq, ck, cv,
                                            cwq, cwk, cwv,
                                            bq, bk, bv,
                                            qh, kh, vh);

    // 2) scores + exp + psum (writes E and upper-tri zeros)
    dim3 gScores(NQT, NQT, BH);                     // (16, 16, 32)
    scores_exp<<<gScores, thr, SMEM_SCORES>>>(qh, kh, attnp, psum);

    // 3) normalize (P write) + O = P @ V  (64-row tiles)
    dim3 gAV(NQT64, BH);                            // (32, 32)
    attnv_v3<<<gAV, thrG, SMEM_AV3>>>(attnp, vh, psum, oh);

    // 4) output projection
    dim3 gOut(SIZE / 128, M_TOK / 128);             // (8, 32)
    outproj_wmma<<<gOut, thrG, SMEM_GEMM>>>(oh, cwo, bo, outp);
}